// round 3
// baseline (speedup 1.0000x reference)
#include <cuda_runtime.h>
#include <cuda_bf16.h>

// Problem constants (from reference)
#define T_TOK 2048
#define KTOP  6
#define NEXP  32
#define DDIM  2048
#define FDIM  1408
#define SSH   2
#define CCAP  384   // T*K/E exact per-expert capacity (balanced routing)
#define NPAIR (T_TOK*KTOP)  // 12288

// ---------------- scratch (device globals: allocation-free) ----------------
__device__ __align__(16) int   g_tok [NEXP*CCAP];                // source token per sorted pair
__device__ __align__(16) float g_wp  [NEXP*CCAP];                // routing weight per sorted pair
__device__ __align__(16) float g_gu  [(size_t)NEXP*CCAP*2*FDIM]; // routed gate_up output
__device__ __align__(16) float g_act [(size_t)NEXP*CCAP*FDIM];   // routed silu*up
__device__ __align__(16) float g_gu_s[(size_t)SSH*T_TOK*2*FDIM]; // shared gate_up output
__device__ __align__(16) float g_act_s[(size_t)SSH*T_TOK*FDIM];  // shared silu*up

// ---------------- dispatch: stable counting sort by expert ----------------
// One block per expert. Each thread scans a contiguous chunk of 48 pairs,
// counts matches, block-exclusive-scans the counts, then rewrites matches in
// order. Contiguous chunks + in-chunk order => stable (matches argsort stable).
__global__ void dispatch_k(const int* __restrict__ idx, const float* __restrict__ wts) {
    const int e = blockIdx.x;       // expert id
    const int t = threadIdx.x;      // 0..255
    const int CH = NPAIR / 256;     // 48
    __shared__ int cnt[256];
    __shared__ int warpsum[8];

    const int base = t * CH;
    int c = 0;
    for (int j = 0; j < CH; ++j) c += (idx[base + j] == e);
    cnt[t] = c;
    __syncthreads();

    // exclusive scan over 256 counts
    int v = cnt[t];
    int lane = t & 31, wid = t >> 5;
    // inclusive warp scan
    #pragma unroll
    for (int o = 1; o < 32; o <<= 1) {
        int n = __shfl_up_sync(0xffffffffu, v, o);
        if (lane >= o) v += n;
    }
    if (lane == 31) warpsum[wid] = v;
    __syncthreads();
    if (t == 0) {
        int run = 0;
        for (int w = 0; w < 8; ++w) { int s = warpsum[w]; warpsum[w] = run; run += s; }
    }
    __syncthreads();
    int pos = v - cnt[t] + warpsum[wid];   // exclusive prefix for this thread

    for (int j = 0; j < CH; ++j) {
        int p = base + j;
        if (idx[p] == e) {
            int dst = e * CCAP + pos;
            g_tok[dst] = p / KTOP;
            g_wp [dst] = wts[p];
            ++pos;
        }
    }
}

// ---------------- tiled SGEMM ----------------
// C[M,N] = A[M,K] * B[K,N], all row-major. Per-z (expert) strides.
// gatherA (optional): A row m reads A[gatherA[z*M+m]*K + k]  (gate_up gather).
// MODE 0: store to C + z*sC at direct rows.
// MODE 1: atomicAdd into C[(scat? scat[z*M+m] : m)*N + n] scaled by wvec.
#define BM 128
#define BN 128
#define BKD 8
#define TM 8
#define TN 8

template<int MODE>
__global__ __launch_bounds__(256, 2)
void gemm_k(const float* __restrict__ A, const float* __restrict__ B,
            float* __restrict__ C,
            const int* __restrict__ gatherA,
            const int* __restrict__ scat, const float* __restrict__ wvec,
            int M, int N, int Kd,
            long sA, long sB, long sC)
{
    const int z = blockIdx.z;
    const float* Ae = A + (size_t)z * sA;
    const float* Be = B + (size_t)z * sB;
    const int*   ga = gatherA ? gatherA + (size_t)z * M : nullptr;
    const int*   sc = scat    ? scat    + (size_t)z * M : nullptr;
    const float* wz = wvec    ? wvec    + (size_t)z * M : nullptr;

    const int bm = blockIdx.y * BM;
    const int bn = blockIdx.x * BN;

    __shared__ float As[BKD][BM];
    __shared__ float Bs[BKD][BN];

    const int tid = threadIdx.x;
    const int tx = tid & 15;        // 16 thread-cols
    const int ty = tid >> 4;        // 16 thread-rows

    // A tile load mapping: 128 rows x 8 k -> one float4 per thread
    const int arow = tid >> 1;
    const int akc  = (tid & 1) * 4;
    const int aRow = bm + arow;
    const float* aptr = Ae + (size_t)(ga ? ga[aRow] : aRow) * Kd + akc;

    // B tile load mapping: 8 k-rows x 128 cols -> one float4 per thread
    const int brow = tid >> 5;
    const int bcol = (tid & 31) * 4;
    const float* bptr = Be + (size_t)brow * N + bn + bcol;

    float acc[TM][TN];
    #pragma unroll
    for (int i = 0; i < TM; ++i)
        #pragma unroll
        for (int j = 0; j < TN; ++j) acc[i][j] = 0.0f;

    for (int k0 = 0; k0 < Kd; k0 += BKD) {
        float4 av = *(const float4*)(aptr + k0);
        As[akc+0][arow] = av.x;
        As[akc+1][arow] = av.y;
        As[akc+2][arow] = av.z;
        As[akc+3][arow] = av.w;
        *(float4*)&Bs[brow][bcol] = *(const float4*)(bptr + (size_t)k0 * N);
        __syncthreads();

        #pragma unroll
        for (int k = 0; k < BKD; ++k) {
            float a[TM], b[TN];
            #pragma unroll
            for (int i = 0; i < TM; ++i) a[i] = As[k][ty*TM + i];
            #pragma unroll
            for (int j = 0; j < TN; ++j) b[j] = Bs[k][tx*TN + j];
            #pragma unroll
            for (int i = 0; i < TM; ++i)
                #pragma unroll
                for (int j = 0; j < TN; ++j)
                    acc[i][j] = fmaf(a[i], b[j], acc[i][j]);
        }
        __syncthreads();
    }

    if (MODE == 0) {
        float* Ce = C + (size_t)z * sC;
        #pragma unroll
        for (int i = 0; i < TM; ++i) {
            float* row = Ce + (size_t)(bm + ty*TM + i) * N + bn + tx*TN;
            *(float4*)(row + 0) = make_float4(acc[i][0], acc[i][1], acc[i][2], acc[i][3]);
            *(float4*)(row + 4) = make_float4(acc[i][4], acc[i][5], acc[i][6], acc[i][7]);
        }
    } else {
        #pragma unroll
        for (int i = 0; i < TM; ++i) {
            int r = bm + ty*TM + i;
            int orow = sc ? sc[r] : r;
            float w = wz ? wz[r] : 1.0f;
            float* row = C + (size_t)orow * N + bn + tx*TN;
            #pragma unroll
            for (int j = 0; j < TN; ++j)
                atomicAdd(row + j, acc[i][j] * w);
        }
    }
}

// ---------------- silu(gate) * up ----------------
__global__ void silu_k(const float* __restrict__ gu, float* __restrict__ act, long nrows) {
    long total = nrows * FDIM;
    for (long i = (long)blockIdx.x * blockDim.x + threadIdx.x; i < total;
         i += (long)gridDim.x * blockDim.x) {
        long r = i / FDIM;
        int f = (int)(i - r * FDIM);
        const float* row = gu + r * (2*FDIM);
        float g = row[f];
        float u = row[FDIM + f];
        act[i] = (g / (1.0f + __expf(-g))) * u;
    }
}

// ---------------- launch ----------------
extern "C" void kernel_launch(void* const* d_in, const int* in_sizes, int n_in,
                              void* d_out, int out_size) {
    const float* x    = (const float*)d_in[0];  // [T, D]
    const float* wts  = (const float*)d_in[1];  // [T, K]
    const float* wgu  = (const float*)d_in[2];  // [E, D, 2F]
    const float* wdn  = (const float*)d_in[3];  // [E, F, D]
    const float* wgus = (const float*)d_in[4];  // [S, D, 2F]
    const float* wdns = (const float*)d_in[5];  // [S, F, D]
    const int*   idx  = (const int*)d_in[6];    // [T, K]
    float* y = (float*)d_out;                   // [T, D]

    float *p_gu, *p_act, *p_gus, *p_acts, *p_wp;
    int* p_tok;
    cudaGetSymbolAddress((void**)&p_gu,   g_gu);
    cudaGetSymbolAddress((void**)&p_act,  g_act);
    cudaGetSymbolAddress((void**)&p_gus,  g_gu_s);
    cudaGetSymbolAddress((void**)&p_acts, g_act_s);
    cudaGetSymbolAddress((void**)&p_tok,  g_tok);
    cudaGetSymbolAddress((void**)&p_wp,   g_wp);

    cudaMemsetAsync(y, 0, (size_t)T_TOK * DDIM * sizeof(float));
    dispatch_k<<<NEXP, 256>>>(idx, wts);

    // routed gate_up: [E] x (gather[C,D] @ [D,2F]) -> g_gu
    gemm_k<0><<<dim3(2*FDIM/BN, CCAP/BM, NEXP), 256>>>(
        x, wgu, p_gu, p_tok, nullptr, nullptr,
        CCAP, 2*FDIM, DDIM, 0L, (long)DDIM*2*FDIM, (long)CCAP*2*FDIM);

    {
        long total = (long)NEXP * CCAP * FDIM;
        int blocks = (int)((total + 255) / 256);
        silu_k<<<blocks, 256>>>(p_gu, p_act, (long)NEXP * CCAP);
    }

    // routed down + weighted scatter-add: [E] x ([C,F] @ [F,D]) -> y[tok] += w*out
    gemm_k<1><<<dim3(DDIM/BN, CCAP/BM, NEXP), 256>>>(
        p_act, wdn, y, nullptr, p_tok, p_wp,
        CCAP, DDIM, FDIM, (long)CCAP*FDIM, (long)FDIM*DDIM, 0L);

    // shared gate_up: [S] x ([T,D] @ [D,2F]) -> g_gu_s
    gemm_k<0><<<dim3(2*FDIM/BN, T_TOK/BM, SSH), 256>>>(
        x, wgus, p_gus, nullptr, nullptr, nullptr,
        T_TOK, 2*FDIM, DDIM, 0L, (long)DDIM*2*FDIM, (long)T_TOK*2*FDIM);

    {
        long total = (long)SSH * T_TOK * FDIM;
        int blocks = (int)((total + 255) / 256);
        silu_k<<<blocks, 256>>>(p_gus, p_acts, (long)SSH * T_TOK);
    }

    // shared down + unweighted add: [S] x ([T,F] @ [F,D]) -> y += out
    gemm_k<1><<<dim3(DDIM/BN, T_TOK/BM, SSH), 256>>>(
        p_acts, wdns, y, nullptr, nullptr, nullptr,
        T_TOK, DDIM, FDIM, (long)T_TOK*FDIM, (long)FDIM*DDIM, 0L);
}

// round 4
// speedup vs baseline: 1.5931x; 1.5931x over previous
#include <cuda_runtime.h>
#include <cuda_bf16.h>

// Problem constants (from reference)
#define T_TOK 2048
#define KTOP  6
#define NEXP  32
#define DDIM  2048
#define FDIM  1408
#define SSH   2
#define CCAP  384   // T*K/E exact per-expert capacity (balanced routing)
#define NPAIR (T_TOK*KTOP)  // 12288

// ---------------- scratch (device globals: allocation-free) ----------------
__device__ __align__(16) int   g_tok [NEXP*CCAP];                // source token per sorted pair
__device__ __align__(16) float g_wp  [NEXP*CCAP];                // routing weight per sorted pair
__device__ __align__(16) float g_gu  [(size_t)NEXP*CCAP*2*FDIM]; // routed gate_up output
__device__ __align__(16) float g_act [(size_t)NEXP*CCAP*FDIM];   // routed silu*up
__device__ __align__(16) float g_gu_s[(size_t)SSH*T_TOK*2*FDIM]; // shared gate_up output
__device__ __align__(16) float g_act_s[(size_t)SSH*T_TOK*FDIM];  // shared silu*up

// ---------------- dispatch: stable counting sort by expert ----------------
// One block per expert. Each thread scans a contiguous chunk of 48 pairs,
// counts matches, block-exclusive-scans the counts, then rewrites matches in
// order. Contiguous chunks + in-chunk order => stable (matches argsort stable).
__global__ void dispatch_k(const int* __restrict__ idx, const float* __restrict__ wts) {
    const int e = blockIdx.x;       // expert id
    const int t = threadIdx.x;      // 0..255
    const int CH = NPAIR / 256;     // 48
    __shared__ int cnt[256];
    __shared__ int warpsum[8];

    const int base = t * CH;
    int c = 0;
    for (int j = 0; j < CH; ++j) c += (idx[base + j] == e);
    cnt[t] = c;
    __syncthreads();

    // exclusive scan over 256 counts
    int v = cnt[t];
    int lane = t & 31, wid = t >> 5;
    // inclusive warp scan
    #pragma unroll
    for (int o = 1; o < 32; o <<= 1) {
        int n = __shfl_up_sync(0xffffffffu, v, o);
        if (lane >= o) v += n;
    }
    if (lane == 31) warpsum[wid] = v;
    __syncthreads();
    if (t == 0) {
        int run = 0;
        for (int w = 0; w < 8; ++w) { int s = warpsum[w]; warpsum[w] = run; run += s; }
    }
    __syncthreads();
    int pos = v - cnt[t] + warpsum[wid];   // exclusive prefix for this thread

    for (int j = 0; j < CH; ++j) {
        int p = base + j;
        if (idx[p] == e) {
            int dst = e * CCAP + pos;
            g_tok[dst] = p / KTOP;
            g_wp [dst] = wts[p];
            ++pos;
        }
    }
}

// ---------------- tiled SGEMM ----------------
// C[M,N] = A[M,K] * B[K,N], all row-major. Per-z (expert) strides.
// gatherA (optional): A row m reads A[gatherA[z*M+m]*K + k]  (gate_up gather).
// MODE 0: store to C + z*sC at direct rows.
// MODE 1: atomicAdd into C[(scat? scat[z*M+m] : m)*N + n] scaled by wvec.
#define BM 128
#define BN 128
#define BKD 8
#define TM 8
#define TN 8

template<int MODE>
__global__ __launch_bounds__(256, 2)
void gemm_k(const float* __restrict__ A, const float* __restrict__ B,
            float* __restrict__ C,
            const int* __restrict__ gatherA,
            const int* __restrict__ scat, const float* __restrict__ wvec,
            int M, int N, int Kd,
            long sA, long sB, long sC)
{
    const int z = blockIdx.z;
    const float* Ae = A + (size_t)z * sA;
    const float* Be = B + (size_t)z * sB;
    const int*   ga = gatherA ? gatherA + (size_t)z * M : nullptr;
    const int*   sc = scat    ? scat    + (size_t)z * M : nullptr;
    const float* wz = wvec    ? wvec    + (size_t)z * M : nullptr;

    const int bm = blockIdx.y * BM;
    const int bn = blockIdx.x * BN;

    __shared__ float As[BKD][BM];
    __shared__ float Bs[BKD][BN];

    const int tid = threadIdx.x;
    const int tx = tid & 15;        // 16 thread-cols
    const int ty = tid >> 4;        // 16 thread-rows

    // A tile load mapping: 128 rows x 8 k -> one float4 per thread
    const int arow = tid >> 1;
    const int akc  = (tid & 1) * 4;
    const int aRow = bm + arow;
    const float* aptr = Ae + (size_t)(ga ? ga[aRow] : aRow) * Kd + akc;

    // B tile load mapping: 8 k-rows x 128 cols -> one float4 per thread
    const int brow = tid >> 5;
    const int bcol = (tid & 31) * 4;
    const float* bptr = Be + (size_t)brow * N + bn + bcol;

    float acc[TM][TN];
    #pragma unroll
    for (int i = 0; i < TM; ++i)
        #pragma unroll
        for (int j = 0; j < TN; ++j) acc[i][j] = 0.0f;

    for (int k0 = 0; k0 < Kd; k0 += BKD) {
        float4 av = *(const float4*)(aptr + k0);
        As[akc+0][arow] = av.x;
        As[akc+1][arow] = av.y;
        As[akc+2][arow] = av.z;
        As[akc+3][arow] = av.w;
        *(float4*)&Bs[brow][bcol] = *(const float4*)(bptr + (size_t)k0 * N);
        __syncthreads();

        #pragma unroll
        for (int k = 0; k < BKD; ++k) {
            float a[TM], b[TN];
            #pragma unroll
            for (int i = 0; i < TM; ++i) a[i] = As[k][ty*TM + i];
            #pragma unroll
            for (int j = 0; j < TN; ++j) b[j] = Bs[k][tx*TN + j];
            #pragma unroll
            for (int i = 0; i < TM; ++i)
                #pragma unroll
                for (int j = 0; j < TN; ++j)
                    acc[i][j] = fmaf(a[i], b[j], acc[i][j]);
        }
        __syncthreads();
    }

    if (MODE == 0) {
        float* Ce = C + (size_t)z * sC;
        #pragma unroll
        for (int i = 0; i < TM; ++i) {
            float* row = Ce + (size_t)(bm + ty*TM + i) * N + bn + tx*TN;
            *(float4*)(row + 0) = make_float4(acc[i][0], acc[i][1], acc[i][2], acc[i][3]);
            *(float4*)(row + 4) = make_float4(acc[i][4], acc[i][5], acc[i][6], acc[i][7]);
        }
    } else {
        #pragma unroll
        for (int i = 0; i < TM; ++i) {
            int r = bm + ty*TM + i;
            int orow = sc ? sc[r] : r;
            float w = wz ? wz[r] : 1.0f;
            float* row = C + (size_t)orow * N + bn + tx*TN;
            #pragma unroll
            for (int j = 0; j < TN; ++j)
                atomicAdd(row + j, acc[i][j] * w);
        }
    }
}

// ---------------- silu(gate) * up ----------------
__global__ void silu_k(const float* __restrict__ gu, float* __restrict__ act, long nrows) {
    long total = nrows * FDIM;
    for (long i = (long)blockIdx.x * blockDim.x + threadIdx.x; i < total;
         i += (long)gridDim.x * blockDim.x) {
        long r = i / FDIM;
        int f = (int)(i - r * FDIM);
        const float* row = gu + r * (2*FDIM);
        float g = row[f];
        float u = row[FDIM + f];
        act[i] = (g / (1.0f + __expf(-g))) * u;
    }
}

// ---------------- launch ----------------
extern "C" void kernel_launch(void* const* d_in, const int* in_sizes, int n_in,
                              void* d_out, int out_size) {
    const float* x    = (const float*)d_in[0];  // [T, D]
    const float* wts  = (const float*)d_in[1];  // [T, K]
    const float* wgu  = (const float*)d_in[2];  // [E, D, 2F]
    const float* wdn  = (const float*)d_in[3];  // [E, F, D]
    const float* wgus = (const float*)d_in[4];  // [S, D, 2F]
    const float* wdns = (const float*)d_in[5];  // [S, F, D]
    const int*   idx  = (const int*)d_in[6];    // [T, K]
    float* y = (float*)d_out;                   // [T, D]

    float *p_gu, *p_act, *p_gus, *p_acts, *p_wp;
    int* p_tok;
    cudaGetSymbolAddress((void**)&p_gu,   g_gu);
    cudaGetSymbolAddress((void**)&p_act,  g_act);
    cudaGetSymbolAddress((void**)&p_gus,  g_gu_s);
    cudaGetSymbolAddress((void**)&p_acts, g_act_s);
    cudaGetSymbolAddress((void**)&p_tok,  g_tok);
    cudaGetSymbolAddress((void**)&p_wp,   g_wp);

    cudaMemsetAsync(y, 0, (size_t)T_TOK * DDIM * sizeof(float));
    dispatch_k<<<NEXP, 256>>>(idx, wts);

    // routed gate_up: [E] x (gather[C,D] @ [D,2F]) -> g_gu
    gemm_k<0><<<dim3(2*FDIM/BN, CCAP/BM, NEXP), 256>>>(
        x, wgu, p_gu, p_tok, nullptr, nullptr,
        CCAP, 2*FDIM, DDIM, 0L, (long)DDIM*2*FDIM, (long)CCAP*2*FDIM);

    {
        long total = (long)NEXP * CCAP * FDIM;
        int blocks = (int)((total + 255) / 256);
        silu_k<<<blocks, 256>>>(p_gu, p_act, (long)NEXP * CCAP);
    }

    // routed down + weighted scatter-add: [E] x ([C,F] @ [F,D]) -> y[tok] += w*out
    gemm_k<1><<<dim3(DDIM/BN, CCAP/BM, NEXP), 256>>>(
        p_act, wdn, y, nullptr, p_tok, p_wp,
        CCAP, DDIM, FDIM, (long)CCAP*FDIM, (long)FDIM*DDIM, 0L);

    // shared gate_up: [S] x ([T,D] @ [D,2F]) -> g_gu_s
    gemm_k<0><<<dim3(2*FDIM/BN, T_TOK/BM, SSH), 256>>>(
        x, wgus, p_gus, nullptr, nullptr, nullptr,
        T_TOK, 2*FDIM, DDIM, 0L, (long)DDIM*2*FDIM, (long)T_TOK*2*FDIM);

    {
        long total = (long)SSH * T_TOK * FDIM;
        int blocks = (int)((total + 255) / 256);
        silu_k<<<blocks, 256>>>(p_gus, p_acts, (long)SSH * T_TOK);
    }

    // shared down + unweighted add: [S] x ([T,F] @ [F,D]) -> y += out
    gemm_k<1><<<dim3(DDIM/BN, T_TOK/BM, SSH), 256>>>(
        p_acts, wdns, y, nullptr, nullptr, nullptr,
        T_TOK, DDIM, FDIM, (long)T_TOK*FDIM, (long)FDIM*DDIM, 0L);
}

// round 7
// speedup vs baseline: 3.2945x; 2.0680x over previous
#include <cuda_runtime.h>
#include <cuda_bf16.h>
#include <cstdint>

// ---------------- problem constants ----------------
#define T_TOK 2048
#define KTOP  6
#define NEXP  32
#define DDIM  2048
#define FDIM  1408
#define SSH   2
#define CCAP  384
#define NPAIR (T_TOK*KTOP)

// ---------------- GEMM tile config ----------------
// CTA 128x128, K-chunk 32, 8 warps (2 M x 4 N), warp tile 64x32, mma.m16n8k16 bf16.
#define SPADE 40                 // padded elems per smem row (80 B)
#define PLANE (128*SPADE*2)      // 10240 B per plane (Ah/Al/Bh/Bl)
#define STG   (4*PLANE)          // 40960 B per stage
#define SMEM_DYN (2*STG)         // 81920 B (double buffered)
#define EPI_LO 18432             // lo-plane offset in epilogue staging (128*72*2)

// ---------------- scratch (device globals) ----------------
__device__ __align__(16) int   g_tok [NEXP*CCAP];
__device__ __align__(16) float g_wp  [NEXP*CCAP];
__device__ __align__(16) __nv_bfloat16 g_xh [(size_t)T_TOK*DDIM];
__device__ __align__(16) __nv_bfloat16 g_xl [(size_t)T_TOK*DDIM];
__device__ __align__(16) __nv_bfloat16 g_acth[(size_t)NEXP*CCAP*FDIM];
__device__ __align__(16) __nv_bfloat16 g_actl[(size_t)NEXP*CCAP*FDIM];
__device__ __align__(16) __nv_bfloat16 g_asth[(size_t)SSH*T_TOK*FDIM];
__device__ __align__(16) __nv_bfloat16 g_astl[(size_t)SSH*T_TOK*FDIM];
__device__ __align__(16) __nv_bfloat16 g_bguh[(size_t)NEXP*2*FDIM*DDIM];
__device__ __align__(16) __nv_bfloat16 g_bgul[(size_t)NEXP*2*FDIM*DDIM];
__device__ __align__(16) __nv_bfloat16 g_bdnh[(size_t)NEXP*DDIM*FDIM];
__device__ __align__(16) __nv_bfloat16 g_bdnl[(size_t)NEXP*DDIM*FDIM];
__device__ __align__(16) __nv_bfloat16 g_bgush[(size_t)SSH*2*FDIM*DDIM];
__device__ __align__(16) __nv_bfloat16 g_bgusl[(size_t)SSH*2*FDIM*DDIM];
__device__ __align__(16) __nv_bfloat16 g_bdnsh[(size_t)SSH*DDIM*FDIM];
__device__ __align__(16) __nv_bfloat16 g_bdnsl[(size_t)SSH*DDIM*FDIM];

// ---------------- PTX helpers (all sm_80+ portable) ----------------
__device__ __forceinline__ uint32_t smem_u32(const void* p) {
    uint32_t a;
    asm("{ .reg .u64 t; cvta.to.shared.u64 t, %1; cvt.u32.u64 %0, t; }" : "=r"(a) : "l"(p));
    return a;
}
__device__ __forceinline__ void cp16(uint32_t dst, const void* src) {
    asm volatile("cp.async.cg.shared.global [%0], [%1], 16;" :: "r"(dst), "l"(src));
}
__device__ __forceinline__ void cp_commit() { asm volatile("cp.async.commit_group;"); }
template<int N> __device__ __forceinline__ void cp_wait() {
    asm volatile("cp.async.wait_group %0;" :: "n"(N));
}
#define LDSM4(r, addr) \
    asm volatile("ldmatrix.sync.aligned.m8n8.x4.shared.b16 {%0,%1,%2,%3},[%4];" \
        : "=r"((r)[0]),"=r"((r)[1]),"=r"((r)[2]),"=r"((r)[3]) : "r"(addr))
#define MMA_BF16(d, a, b) \
    asm volatile("mma.sync.aligned.m16n8k16.row.col.f32.bf16.bf16.f32 " \
        "{%0,%1,%2,%3},{%4,%5,%6,%7},{%8,%9},{%0,%1,%2,%3};" \
        : "+f"((d)[0]),"+f"((d)[1]),"+f"((d)[2]),"+f"((d)[3]) \
        : "r"((a)[0]),"r"((a)[1]),"r"((a)[2]),"r"((a)[3]),"r"((b)[0]),"r"((b)[1]))
__device__ __forceinline__ void red_add_v2(float* p, float a, float b) {
    asm volatile("red.global.add.v2.f32 [%0], {%1,%2};" :: "l"(p), "f"(a), "f"(b) : "memory");
}

// ---------------- dispatch: stable counting sort ----------------
__global__ void dispatch_k(const int* __restrict__ idx, const float* __restrict__ wts) {
    const int e = blockIdx.x, t = threadIdx.x;
    const int CH = NPAIR / 256;
    __shared__ int cnt[256];
    __shared__ int warpsum[8];
    const int base = t * CH;
    int c = 0;
    for (int j = 0; j < CH; ++j) c += (idx[base + j] == e);
    cnt[t] = c;
    __syncthreads();
    int v = cnt[t];
    int lane = t & 31, wid = t >> 5;
    #pragma unroll
    for (int o = 1; o < 32; o <<= 1) {
        int n = __shfl_up_sync(0xffffffffu, v, o);
        if (lane >= o) v += n;
    }
    if (lane == 31) warpsum[wid] = v;
    __syncthreads();
    if (t == 0) { int run = 0; for (int w = 0; w < 8; ++w) { int s = warpsum[w]; warpsum[w] = run; run += s; } }
    __syncthreads();
    int pos = v - cnt[t] + warpsum[wid];
    for (int j = 0; j < CH; ++j) {
        int p = base + j;
        if (idx[p] == e) {
            g_tok[e*CCAP + pos] = p / KTOP;
            g_wp [e*CCAP + pos] = wts[p];
            ++pos;
        }
    }
}

// ---------------- fp32 -> bf16 hi/lo elementwise ----------------
__global__ void convx_k(const float* __restrict__ in, __nv_bfloat16* __restrict__ oh,
                        __nv_bfloat16* __restrict__ ol, long n) {
    long i = (long)blockIdx.x * blockDim.x + threadIdx.x;
    if (i < n) {
        float v = in[i];
        __nv_bfloat16 h = __float2bfloat16(v);
        oh[i] = h;
        ol[i] = __float2bfloat16(v - __bfloat162float(h));
    }
}

// ---------------- weight transpose + split ----------------
// in: [Z, R, Cc] fp32 -> out planes [Z, Cc, R] bf16.
// INTER: out row for src col c: c<Cc/2 -> 2c (gate), else 2(c-Cc/2)+1 (up).
template<int INTER>
__global__ void tconv_k(const float* __restrict__ in, __nv_bfloat16* __restrict__ oh,
                        __nv_bfloat16* __restrict__ ol, int R, int Cc) {
    __shared__ float tile[32][33];
    const int r0 = blockIdx.x * 32, c0 = blockIdx.y * 32;
    const int tx = threadIdx.x, ty = threadIdx.y;
    const size_t zb = (size_t)blockIdx.z * R * Cc;
    #pragma unroll
    for (int i = 0; i < 4; ++i)
        tile[ty + 8*i][tx] = in[zb + (size_t)(r0 + ty + 8*i) * Cc + c0 + tx];
    __syncthreads();
    #pragma unroll
    for (int i = 0; i < 4; ++i) {
        int c = c0 + ty + 8*i;
        int orow = INTER ? ((c < Cc/2) ? 2*c : 2*(c - Cc/2) + 1) : c;
        float v = tile[tx][ty + 8*i];
        __nv_bfloat16 h = __float2bfloat16(v);
        size_t o = zb + (size_t)orow * R + r0 + tx;
        oh[o] = h;
        ol[o] = __float2bfloat16(v - __bfloat162float(h));
    }
}

// ---------------- HMMA grouped GEMM (bf16 hi/lo 3-term) ----------------
// A planes [*, K] (K contiguous), B planes per z [Ntot, K] (K contiguous).
// Both A and B tiles are K-major in smem -> BOTH use non-trans ldmatrix.
// MODE 0: epilogue silu on (even,odd) col pairs -> Oh/Ol act planes.
// MODE 1: epilogue w * val red-add into Y rows (scat).
template<int MODE>
__global__ __launch_bounds__(256, 1)
void hmma_gemm(const __nv_bfloat16* __restrict__ Ah, const __nv_bfloat16* __restrict__ Al,
               const __nv_bfloat16* __restrict__ Bh, const __nv_bfloat16* __restrict__ Bl,
               __nv_bfloat16* __restrict__ Oh, __nv_bfloat16* __restrict__ Ol,
               float* __restrict__ Y,
               const int* __restrict__ gatherA, const int* __restrict__ scat,
               const float* __restrict__ wvec,
               int K, int aZ, int oZ, long bZ, int Mz, int outStride)
{
    extern __shared__ char smem[];
    const uint32_t sb = smem_u32(smem);
    const int tid = threadIdx.x, lane = tid & 31, wid = tid >> 5;
    const int warp_m = wid & 1, warp_n = wid >> 1;        // 2 x 4 warps
    const int z = blockIdx.z, m0 = blockIdx.y * 128, n0 = blockIdx.x * 128;

    // -------- global->smem load mapping (per thread: one row, one 32B k-seg per plane)
    const int lrow = tid >> 1, kh = tid & 1;
    const int aRow = gatherA ? gatherA[z*Mz + m0 + lrow] : (aZ*z + m0 + lrow);
    const __nv_bfloat16* aH = Ah + (size_t)aRow * K + kh*16;
    const __nv_bfloat16* aL = Al + (size_t)aRow * K + kh*16;
    const __nv_bfloat16* bH = Bh + (size_t)z*bZ + (size_t)(n0 + lrow) * K + kh*16;
    const __nv_bfloat16* bL = Bl + (size_t)z*bZ + (size_t)(n0 + lrow) * K + kh*16;
    const uint32_t doff = (uint32_t)(lrow * (SPADE*2) + kh*32);

    const int nch = K / 32;
    {   // prime stage 0
        uint32_t d = sb + doff;
        cp16(d,           aH); cp16(d+16,           aH+8);
        cp16(d+PLANE,     aL); cp16(d+PLANE+16,     aL+8);
        cp16(d+2*PLANE,   bH); cp16(d+2*PLANE+16,   bH+8);
        cp16(d+3*PLANE,   bL); cp16(d+3*PLANE+16,   bL+8);
        cp_commit();
    }

    float acc[4][4][4];
    #pragma unroll
    for (int i = 0; i < 4; ++i)
        #pragma unroll
        for (int j = 0; j < 4; ++j)
            #pragma unroll
            for (int q = 0; q < 4; ++q) acc[i][j][q] = 0.0f;

    // -------- fragment load addressing (identical pattern for A and B: K-major)
    // lane -> row (lane&7) + 8*((lane>>3)&1), k-byte (lane>>4)*16
    const int  arow_l = warp_m*64 + (lane & 7) + 8*((lane >> 3) & 1);
    const int  bn_l   = warp_n*32 + (lane & 7) + 8*((lane >> 3) & 1);
    const uint32_t khb = (uint32_t)((lane >> 4) * 16);           // bytes

    for (int s = 0; s < nch; ++s) {
        if (s + 1 < nch) {
            const int kk = (s+1)*32;
            uint32_t d = sb + (uint32_t)((s+1)&1)*STG + doff;
            cp16(d,           aH+kk); cp16(d+16,           aH+kk+8);
            cp16(d+PLANE,     aL+kk); cp16(d+PLANE+16,     aL+kk+8);
            cp16(d+2*PLANE,   bH+kk); cp16(d+2*PLANE+16,   bH+kk+8);
            cp16(d+3*PLANE,   bL+kk); cp16(d+3*PLANE+16,   bL+kk+8);
            cp_commit();
            cp_wait<1>();
        } else {
            cp_wait<0>();
        }
        __syncthreads();
        const uint32_t stg = sb + (uint32_t)(s & 1) * STG;

        #pragma unroll
        for (int ks = 0; ks < 2; ++ks) {
            const uint32_t kb = (uint32_t)(ks * 32);   // bytes: 16 elems * 2B
            uint32_t ah[4][4], al[4][4], bh[4][2], bl[4][2];
            #pragma unroll
            for (int i = 0; i < 4; ++i) {
                uint32_t ad = stg + (uint32_t)((arow_l + i*16) * (SPADE*2)) + kb + khb;
                LDSM4(ah[i], ad);
                LDSM4(al[i], ad + PLANE);
            }
            #pragma unroll
            for (int jj = 0; jj < 2; ++jj) {
                uint32_t bd = stg + 2*PLANE + (uint32_t)((bn_l + jj*16) * (SPADE*2)) + kb + khb;
                uint32_t rb[4], rbl[4];
                LDSM4(rb, bd);
                LDSM4(rbl, bd + PLANE);
                // non-trans x4 of [n][k]: r0=nLo/kLo r1=nHi/kLo r2=nLo/kHi r3=nHi/kHi
                bh[2*jj][0]   = rb[0];  bh[2*jj][1]   = rb[2];
                bh[2*jj+1][0] = rb[1];  bh[2*jj+1][1] = rb[3];
                bl[2*jj][0]   = rbl[0]; bl[2*jj][1]   = rbl[2];
                bl[2*jj+1][0] = rbl[1]; bl[2*jj+1][1] = rbl[3];
            }
            #pragma unroll
            for (int i = 0; i < 4; ++i)
                #pragma unroll
                for (int j = 0; j < 4; ++j) {
                    MMA_BF16(acc[i][j], ah[i], bh[j]);
                    MMA_BF16(acc[i][j], ah[i], bl[j]);
                    MMA_BF16(acc[i][j], al[i], bh[j]);
                }
        }
        __syncthreads();
    }

    // ---------------- epilogue ----------------
    // c-frag map (m16n8): c0:(r, c) c1:(r, c+1) c2:(r+8, c) c3:(r+8, c+1)
    // with r = lane/4, c = (lane%4)*2; frag j covers n-offset j*8.
    if (MODE == 0) {
        #pragma unroll
        for (int i = 0; i < 4; ++i)
            #pragma unroll
            for (int j = 0; j < 4; ++j) {
                int p  = warp_n*16 + j*4 + (lane & 3);          // local pair idx (0..63)
                int r0 = warp_m*64 + i*16 + (lane >> 2);
                float g0 = acc[i][j][0], u0 = acc[i][j][1];
                float a0 = (g0 / (1.0f + __expf(-g0))) * u0;
                float g1 = acc[i][j][2], u1 = acc[i][j][3];
                float a1 = (g1 / (1.0f + __expf(-g1))) * u1;
                __nv_bfloat16 h0 = __float2bfloat16(a0);
                __nv_bfloat16 l0 = __float2bfloat16(a0 - __bfloat162float(h0));
                __nv_bfloat16 h1 = __float2bfloat16(a1);
                __nv_bfloat16 l1 = __float2bfloat16(a1 - __bfloat162float(h1));
                *(__nv_bfloat16*)(smem + (size_t)(r0*72 + p)*2)            = h0;
                *(__nv_bfloat16*)(smem + EPI_LO + (size_t)(r0*72 + p)*2)   = l0;
                *(__nv_bfloat16*)(smem + (size_t)((r0+8)*72 + p)*2)        = h1;
                *(__nv_bfloat16*)(smem + EPI_LO + (size_t)((r0+8)*72 + p)*2) = l1;
            }
        __syncthreads();
        const int r = tid >> 1, hx = tid & 1;
        const size_t orow = (size_t)oZ * z + m0 + r;
        __nv_bfloat16* dh = Oh + orow * outStride + n0/2 + hx*32;
        __nv_bfloat16* dl = Ol + orow * outStride + n0/2 + hx*32;
        #pragma unroll
        for (int c = 0; c < 4; ++c) {
            *(uint4*)(dh + 8*c) = *(const uint4*)(smem + (size_t)(r*72 + hx*32 + 8*c)*2);
            *(uint4*)(dl + 8*c) = *(const uint4*)(smem + EPI_LO + (size_t)(r*72 + hx*32 + 8*c)*2);
        }
    } else {
        #pragma unroll
        for (int i = 0; i < 4; ++i) {
            const int ml0 = m0 + warp_m*64 + i*16 + (lane >> 2);
            const int ml1 = ml0 + 8;
            const int gi0 = z*Mz + ml0, gi1 = z*Mz + ml1;
            const int o0 = scat ? scat[gi0] : ml0;
            const int o1 = scat ? scat[gi1] : ml1;
            const float w0 = wvec ? wvec[gi0] : 1.0f;
            const float w1 = wvec ? wvec[gi1] : 1.0f;
            #pragma unroll
            for (int j = 0; j < 4; ++j) {
                const int ncol = n0 + warp_n*32 + j*8 + (lane & 3)*2;
                red_add_v2(Y + (size_t)o0 * outStride + ncol,
                           acc[i][j][0]*w0, acc[i][j][1]*w0);
                red_add_v2(Y + (size_t)o1 * outStride + ncol,
                           acc[i][j][2]*w1, acc[i][j][3]*w1);
            }
        }
    }
}

// ---------------- launch ----------------
extern "C" void kernel_launch(void* const* d_in, const int* in_sizes, int n_in,
                              void* d_out, int out_size) {
    const float* x    = (const float*)d_in[0];
    const float* wts  = (const float*)d_in[1];
    const float* wgu  = (const float*)d_in[2];
    const float* wdn  = (const float*)d_in[3];
    const float* wgus = (const float*)d_in[4];
    const float* wdns = (const float*)d_in[5];
    const int*   idx  = (const int*)d_in[6];
    float* y = (float*)d_out;

    cudaFuncSetAttribute(hmma_gemm<0>, cudaFuncAttributeMaxDynamicSharedMemorySize, SMEM_DYN);
    cudaFuncSetAttribute(hmma_gemm<1>, cudaFuncAttributeMaxDynamicSharedMemorySize, SMEM_DYN);

    __nv_bfloat16 *p_xh, *p_xl, *p_acth, *p_actl, *p_asth, *p_astl;
    __nv_bfloat16 *p_bguh, *p_bgul, *p_bdnh, *p_bdnl, *p_bgush, *p_bgusl, *p_bdnsh, *p_bdnsl;
    int* p_tok; float* p_wp;
    cudaGetSymbolAddress((void**)&p_xh, g_xh);     cudaGetSymbolAddress((void**)&p_xl, g_xl);
    cudaGetSymbolAddress((void**)&p_acth, g_acth); cudaGetSymbolAddress((void**)&p_actl, g_actl);
    cudaGetSymbolAddress((void**)&p_asth, g_asth); cudaGetSymbolAddress((void**)&p_astl, g_astl);
    cudaGetSymbolAddress((void**)&p_bguh, g_bguh); cudaGetSymbolAddress((void**)&p_bgul, g_bgul);
    cudaGetSymbolAddress((void**)&p_bdnh, g_bdnh); cudaGetSymbolAddress((void**)&p_bdnl, g_bdnl);
    cudaGetSymbolAddress((void**)&p_bgush, g_bgush); cudaGetSymbolAddress((void**)&p_bgusl, g_bgusl);
    cudaGetSymbolAddress((void**)&p_bdnsh, g_bdnsh); cudaGetSymbolAddress((void**)&p_bdnsl, g_bdnsl);
    cudaGetSymbolAddress((void**)&p_tok, g_tok);   cudaGetSymbolAddress((void**)&p_wp, g_wp);

    cudaMemsetAsync(y, 0, (size_t)T_TOK * DDIM * sizeof(float));
    dispatch_k<<<NEXP, 256>>>(idx, wts);

    // conversions
    {
        long n = (long)T_TOK * DDIM;
        convx_k<<<(int)((n + 255)/256), 256>>>(x, p_xh, p_xl, n);
    }
    tconv_k<1><<<dim3(DDIM/32, 2*FDIM/32, NEXP), dim3(32,8)>>>(wgu,  p_bguh,  p_bgul,  DDIM, 2*FDIM);
    tconv_k<0><<<dim3(FDIM/32, DDIM/32,  NEXP), dim3(32,8)>>>(wdn,  p_bdnh,  p_bdnl,  FDIM, DDIM);
    tconv_k<1><<<dim3(DDIM/32, 2*FDIM/32, SSH),  dim3(32,8)>>>(wgus, p_bgush, p_bgusl, DDIM, 2*FDIM);
    tconv_k<0><<<dim3(FDIM/32, DDIM/32,  SSH),  dim3(32,8)>>>(wdns, p_bdnsh, p_bdnsl, FDIM, DDIM);

    // G1: routed gate_up + silu -> act planes   (M=CCAP, N=2F interleaved, K=D)
    hmma_gemm<0><<<dim3(2*FDIM/128, CCAP/128, NEXP), 256, SMEM_DYN>>>(
        p_xh, p_xl, p_bguh, p_bgul, p_acth, p_actl, nullptr,
        p_tok, nullptr, nullptr, DDIM, 0, CCAP, (long)2*FDIM*DDIM, CCAP, FDIM);

    // G2: routed down -> weighted scatter-add into y   (M=CCAP, N=D, K=F)
    hmma_gemm<1><<<dim3(DDIM/128, CCAP/128, NEXP), 256, SMEM_DYN>>>(
        p_acth, p_actl, p_bdnh, p_bdnl, nullptr, nullptr, y,
        nullptr, p_tok, p_wp, FDIM, CCAP, 0, (long)DDIM*FDIM, CCAP, DDIM);

    // G3: shared gate_up + silu -> shared act planes   (M=T, N=2F, K=D)
    hmma_gemm<0><<<dim3(2*FDIM/128, T_TOK/128, SSH), 256, SMEM_DYN>>>(
        p_xh, p_xl, p_bgush, p_bgusl, p_asth, p_astl, nullptr,
        nullptr, nullptr, nullptr, DDIM, 0, T_TOK, (long)2*FDIM*DDIM, T_TOK, FDIM);

    // G4: shared down -> add into y   (M=T, N=D, K=F)
    hmma_gemm<1><<<dim3(DDIM/128, T_TOK/128, SSH), 256, SMEM_DYN>>>(
        p_asth, p_astl, p_bdnsh, p_bdnsl, nullptr, nullptr, y,
        nullptr, nullptr, nullptr, FDIM, T_TOK, 0, (long)DDIM*FDIM, T_TOK, DDIM);
}